// round 17
// baseline (speedup 1.0000x reference)
#include <cuda_runtime.h>
#include <cuda_bf16.h>
#include <stdint.h>

// Problem constants
#define BB 16
#define SS 1024
#define DD 1024
#define HH 16
#define DK 64
#define MTOK (BB*SS)          // 16384 token rows

// Scratch buffers (device globals — no allocation allowed)
__device__ float g_A[(size_t)MTOK * DD];
__device__ float g_B[(size_t)MTOK * DD];
__device__ float g_C[(size_t)MTOK * DD];
// split-bf16 activation buffers (hi/lo) for attention path
__device__ __nv_bfloat16 g_bf[(size_t)3 * 2 * MTOK * DD];
// int8 two-word activation buffers: 3 slots x (i1,i0)
__device__ int8_t g_i8[(size_t)3 * 2 * MTOK * DD];
__device__ float  g_as[(size_t)3 * MTOK];
// int8 weights: 6 x (i1,i0) [N,K] + per-N scales
__device__ int8_t g_w8[(size_t)6 * 2 * DD * DD];
__device__ float  g_ws[(size_t)6 * DD];

// ===========================================================================
// Helpers
// ===========================================================================
__device__ __forceinline__ uint32_t smem_u32(const void* p) {
    uint32_t a;
    asm("{ .reg .u64 t; cvta.to.shared.u64 t, %1; cvt.u32.u64 %0, t; }" : "=r"(a) : "l"(p));
    return a;
}

#define LDSM_X4(R0, R1, R2, R3, addr)                                          \
    asm volatile("ldmatrix.sync.aligned.m8n8.x4.shared.b16 {%0,%1,%2,%3}, [%4];" \
        : "=r"(R0), "=r"(R1), "=r"(R2), "=r"(R3) : "r"(addr))

__device__ __forceinline__ void mma16816(float* d, const uint32_t* a, const uint32_t* b) {
    asm volatile(
        "mma.sync.aligned.m16n8k16.row.col.f32.bf16.bf16.f32 "
        "{%0,%1,%2,%3}, {%4,%5,%6,%7}, {%8,%9}, {%0,%1,%2,%3};"
        : "+f"(d[0]), "+f"(d[1]), "+f"(d[2]), "+f"(d[3])
        : "r"(a[0]), "r"(a[1]), "r"(a[2]), "r"(a[3]), "r"(b[0]), "r"(b[1]));
}

// int8 k32 MMA, s32 accumulate. Fragments are byte-identical to the bf16-k16
// ldmatrix fragments (each b16 = 2 consecutive int8 along k).
__device__ __forceinline__ void mma_s8(int* d, const uint32_t* a, const uint32_t* b) {
    asm volatile(
        "mma.sync.aligned.m16n8k32.row.col.s32.s8.s8.s32 "
        "{%0,%1,%2,%3}, {%4,%5,%6,%7}, {%8,%9}, {%0,%1,%2,%3};"
        : "+r"(d[0]), "+r"(d[1]), "+r"(d[2]), "+r"(d[3])
        : "r"(a[0]), "r"(a[1]), "r"(a[2]), "r"(a[3]), "r"(b[0]), "r"(b[1]));
}

__device__ __forceinline__ void split2(float a, float b, uint32_t& hi, uint32_t& lo) {
    __nv_bfloat16 ah = __float2bfloat16_rn(a);
    __nv_bfloat16 bh = __float2bfloat16_rn(b);
    __nv_bfloat16 al = __float2bfloat16_rn(a - __bfloat162float(ah));
    __nv_bfloat16 bl = __float2bfloat16_rn(b - __bfloat162float(bh));
    hi = (uint32_t)__bfloat16_as_ushort(ah) | ((uint32_t)__bfloat16_as_ushort(bh) << 16);
    lo = (uint32_t)__bfloat16_as_ushort(al) | ((uint32_t)__bfloat16_as_ushort(bl) << 16);
}

#define CP16(sm, gm) asm volatile("cp.async.cg.shared.global [%0], [%1], 16;" :: "r"(sm), "l"(gm))
#define CP_COMMIT()  asm volatile("cp.async.commit_group;")
#define CP_WAIT0()   asm volatile("cp.async.wait_group 0;" ::: "memory")
#define CP_WAIT1()   asm volatile("cp.async.wait_group 1;" ::: "memory")

// ===========================================================================
// Prep kernels
// ===========================================================================
// W [K,N] fp32 -> Wt [N,K] fp32 (transpose via smem)
__global__ void transpose_w(const float* __restrict__ W, float* __restrict__ Wt)
{
    __shared__ float t[32][33];
    const int n0 = blockIdx.x * 32;
    const int k0 = blockIdx.y * 32;
    const int tx = threadIdx.x, ty = threadIdx.y;
    #pragma unroll
    for (int j = ty; j < 32; j += 8)
        t[j][tx] = W[(size_t)(k0 + j) * DD + n0 + tx];
    __syncthreads();
    #pragma unroll
    for (int j = ty; j < 32; j += 8)
        Wt[(size_t)(n0 + j) * DD + k0 + tx] = t[tx][j];
}

// Per-row two-word int8 quantization: x = qs * (i1*128 + i0), |i| <= 16256.
__global__ void __launch_bounds__(256) quant_rows(
    const float* __restrict__ X,
    int8_t* __restrict__ I1, int8_t* __restrict__ I0, float* __restrict__ qs)
{
    const int row = blockIdx.x;
    const int tid = threadIdx.x;
    const float4 v = ((const float4*)(X + (size_t)row * DD))[tid];
    float am = fmaxf(fmaxf(fabsf(v.x), fabsf(v.y)), fmaxf(fabsf(v.z), fabsf(v.w)));
    #pragma unroll
    for (int off = 16; off; off >>= 1)
        am = fmaxf(am, __shfl_xor_sync(0xffffffffu, am, off));
    __shared__ float sam[8];
    if ((tid & 31) == 0) sam[tid >> 5] = am;
    __syncthreads();
    float amax = 0.f;
    #pragma unroll
    for (int i = 0; i < 8; i++) amax = fmaxf(amax, sam[i]);
    const float inv = (amax > 0.f) ? (16256.0f / amax) : 0.f;
    if (tid == 0) qs[row] = amax * (1.0f / 16256.0f);

    const float vv[4] = {v.x, v.y, v.z, v.w};
    uint32_t u1 = 0, u0 = 0;
    #pragma unroll
    for (int j = 0; j < 4; j++) {
        const int ia = __float2int_rn(vv[j] * inv);
        const int i1 = (ia + 64) >> 7;          // arithmetic shift: floor((ia+64)/128)
        const int i0 = ia - (i1 << 7);          // in [-64, 63]
        u1 |= ((uint32_t)(uint8_t)(int8_t)i1) << (j * 8);
        u0 |= ((uint32_t)(uint8_t)(int8_t)i0) << (j * 8);
    }
    ((uint32_t*)(I1 + (size_t)row * DD))[tid] = u1;
    ((uint32_t*)(I0 + (size_t)row * DD))[tid] = u0;
}

// ===========================================================================
// int8 two-word GEMM: C = A[M,K] @ B^T (B stored [N,K]).
// CTA 128x128, 512 threads / 16 warps (4x4), warp tile 32x32.
// BK=64 int8 (2 k32 steps), 3-stage cp.async pipeline.
// C = qsA[row]*qsB[col]*(16384*S1 + 128*Smid); S00 term dropped (~3e-5 rel).
// ===========================================================================
#define I8_RSTRIDE 80                      // 64 int8 + 16 pad (conflict-free LDSM)
#define I8_T (128 * I8_RSTRIDE)            // 10240
#define I8_STG (4 * I8_T)                  // 40960
#define I8_SMEM (3 * I8_STG)               // 122880
#define NCH8 (DD / 64)                     // 16

template<bool BIAS, bool RELU, bool OUTF32, bool OUTSPLIT>
__global__ void __launch_bounds__(512, 1) gemm_i8(
    const int8_t* __restrict__ A1, const int8_t* __restrict__ A0,
    const float* __restrict__ qsA,
    const int8_t* __restrict__ B1, const int8_t* __restrict__ B0,
    const float* __restrict__ qsB,
    const float* __restrict__ bias,
    float* __restrict__ Cf,
    __nv_bfloat16* __restrict__ Ch, __nv_bfloat16* __restrict__ Cl)
{
    extern __shared__ char smem[];
    const uint32_t sbase = smem_u32(smem);
    const int tid  = threadIdx.x;
    const int lane = tid & 31;
    const int wid  = tid >> 5;           // 0..15
    const int wm   = wid & 3;            // 4 m-warps * 32 rows
    const int wn   = wid >> 2;           // 4 n-warps * 32 cols
    const int n0   = blockIdx.x * 128;
    const int m0   = blockIdx.y * 128;

    int s1[2][4][4] = {};                // i1*i1 accumulators
    int sm_[2][4][4] = {};               // i1*i0 + i0*i1 accumulators

    auto issue = [&](int c, int s) {
        const int k0 = c * 64;
        const uint32_t st = sbase + s * I8_STG;
        #pragma unroll
        for (int i = 0; i < 4; i++) {
            const int id   = tid + 512 * i;            // 0..2047
            const int tile = id >> 9;                  // 0:A1 1:A0 2:B1 3:B0
            const int r    = (id >> 2) & 127;
            const int seg  = id & 3;
            const int8_t* g =
                (tile == 0 ? A1 : tile == 1 ? A0 : tile == 2 ? B1 : B0)
                + (size_t)((tile < 2 ? m0 : n0) + r) * DD + k0 + seg * 16;
            CP16(st + tile * I8_T + r * I8_RSTRIDE + seg * 16, g);
        }
    };

    const int arow   = lane & 15;
    const int acb    = (lane >> 4) * 16;
    const int qq     = lane >> 3;
    const int lr     = lane & 7;
    const int brow_q = ((qq & 2) ? 8 : 0) + lr;
    const int bcb    = (qq & 1) * 16;

    auto compute = [&](uint32_t stg) {
        const uint32_t sA1 = stg;
        const uint32_t sA0 = stg + I8_T;
        const uint32_t sB1 = stg + 2 * I8_T;
        const uint32_t sB0 = stg + 3 * I8_T;
        #pragma unroll
        for (int ks = 0; ks < 2; ks++) {          // 2 x k32 per 64-byte chunk
            const int kb = ks * 32;
            uint32_t a1f[2][4], a0f[2][4], b1f[2][4], b0f[2][4];
            #pragma unroll
            for (int mt = 0; mt < 2; mt++) {
                const uint32_t off = (uint32_t)((wm * 32 + mt * 16 + arow) * I8_RSTRIDE + kb + acb);
                LDSM_X4(a1f[mt][0], a1f[mt][1], a1f[mt][2], a1f[mt][3], sA1 + off);
                LDSM_X4(a0f[mt][0], a0f[mt][1], a0f[mt][2], a0f[mt][3], sA0 + off);
            }
            #pragma unroll
            for (int p = 0; p < 2; p++) {
                const uint32_t off = (uint32_t)((wn * 32 + p * 16 + brow_q) * I8_RSTRIDE + kb + bcb);
                LDSM_X4(b1f[p][0], b1f[p][1], b1f[p][2], b1f[p][3], sB1 + off);
                LDSM_X4(b0f[p][0], b0f[p][1], b0f[p][2], b0f[p][3], sB0 + off);
            }
            // S1 += i1A * i1B
            #pragma unroll
            for (int mt = 0; mt < 2; mt++)
                #pragma unroll
                for (int p = 0; p < 2; p++)
                    #pragma unroll
                    for (int h = 0; h < 2; h++)
                        mma_s8(s1[mt][p * 2 + h], a1f[mt], &b1f[p][h * 2]);
            // Smid += i1A * i0B
            #pragma unroll
            for (int mt = 0; mt < 2; mt++)
                #pragma unroll
                for (int p = 0; p < 2; p++)
                    #pragma unroll
                    for (int h = 0; h < 2; h++)
                        mma_s8(sm_[mt][p * 2 + h], a1f[mt], &b0f[p][h * 2]);
            // Smid += i0A * i1B
            #pragma unroll
            for (int mt = 0; mt < 2; mt++)
                #pragma unroll
                for (int p = 0; p < 2; p++)
                    #pragma unroll
                    for (int h = 0; h < 2; h++)
                        mma_s8(sm_[mt][p * 2 + h], a0f[mt], &b1f[p][h * 2]);
        }
    };

    // 3-stage pipeline: 2 chunks in flight
    issue(0, 0); CP_COMMIT();
    issue(1, 1); CP_COMMIT();
    for (int c = 0; c < NCH8; c++) {
        CP_WAIT1();
        __syncthreads();
        if (c + 2 < NCH8) issue(c + 2, (c + 2) % 3);
        CP_COMMIT();
        compute(sbase + (c % 3) * I8_STG);
    }

    // Epilogue
    #pragma unroll
    for (int mt = 0; mt < 2; mt++) {
        const int row = m0 + wm * 32 + mt * 16 + (lane >> 2);
        const float sa0 = qsA[row];
        const float sa1 = qsA[row + 8];
        #pragma unroll
        for (int nt = 0; nt < 4; nt++) {
            const int col = n0 + wn * 32 + nt * 8 + (lane & 3) * 2;
            const float sw0 = qsB[col];
            const float sw1 = qsB[col + 1];
            const int* S = s1[mt][nt];
            const int* M = sm_[mt][nt];
            float b0 = 0.f, b1 = 0.f;
            if (BIAS) { b0 = __ldg(bias + col); b1 = __ldg(bias + col + 1); }
            float2 v01, v23;
            v01.x = sa0 * sw0 * (16384.f * (float)S[0] + 128.f * (float)M[0]) + b0;
            v01.y = sa0 * sw1 * (16384.f * (float)S[1] + 128.f * (float)M[1]) + b1;
            v23.x = sa1 * sw0 * (16384.f * (float)S[2] + 128.f * (float)M[2]) + b0;
            v23.y = sa1 * sw1 * (16384.f * (float)S[3] + 128.f * (float)M[3]) + b1;
            if (RELU) {
                v01.x = fmaxf(v01.x, 0.f); v01.y = fmaxf(v01.y, 0.f);
                v23.x = fmaxf(v23.x, 0.f); v23.y = fmaxf(v23.y, 0.f);
            }
            if (OUTF32) {
                *(float2*)(Cf + (size_t)row * DD + col)       = v01;
                *(float2*)(Cf + (size_t)(row + 8) * DD + col) = v23;
            }
            if (OUTSPLIT) {
                uint32_t h, l;
                split2(v01.x, v01.y, h, l);
                *(uint32_t*)(Ch + (size_t)row * DD + col) = h;
                *(uint32_t*)(Cl + (size_t)row * DD + col) = l;
                split2(v23.x, v23.y, h, l);
                *(uint32_t*)(Ch + (size_t)(row + 8) * DD + col) = h;
                *(uint32_t*)(Cl + (size_t)(row + 8) * DD + col) = l;
            }
        }
    }
}

// ===========================================================================
// Tensor-core flash attention (split-bf16, verified) — epilogue now fp32 ctx.
// ===========================================================================
#define AST 72
#define QTILE_B (128 * AST * 2)            // 18432
#define KTILE_B (64 * AST * 2)             // 9216
#define KVSTG (4 * KTILE_B)                // 36864
#define ATT_SMEM (2 * QTILE_B + 2 * KVSTG) // 110592

__global__ void __launch_bounds__(256) attn_mma_kernel(
    const __nv_bfloat16* __restrict__ Qh_, const __nv_bfloat16* __restrict__ Ql_,
    const __nv_bfloat16* __restrict__ Kh_, const __nv_bfloat16* __restrict__ Kl_,
    const __nv_bfloat16* __restrict__ Vh_, const __nv_bfloat16* __restrict__ Vl_,
    const unsigned char* __restrict__ mask,
    float* __restrict__ ctx)
{
    extern __shared__ char sm[];
    const uint32_t sb = smem_u32(sm);
    const int tid  = threadIdx.x;
    const int lane = tid & 31;
    const int w    = tid >> 5;
    const int qt   = blockIdx.x;           // 0..7
    const int bh   = blockIdx.y;
    const int b    = bh >> 4;
    const int h    = bh & 15;

    const uint32_t uQh = sb;
    const uint32_t uQl = sb + QTILE_B;
    const uint32_t kvBase = sb + 2 * QTILE_B;

    const size_t base = (size_t)b * SS * DD + (size_t)h * DK;

    #pragma unroll
    for (int i = 0; i < 8; i++) {
        const int id   = tid + 256 * i;
        const int tile = id >> 10;
        const int r    = (id >> 3) & 127;
        const int seg  = id & 7;
        const __nv_bfloat16* g = (tile ? Ql_ : Qh_)
            + base + (size_t)(qt * 128 + r) * DD + seg * 8;
        CP16(sb + tile * QTILE_B + r * 144 + seg * 16, g);
    }
    CP_COMMIT();

    auto issueK = [&](int kt, int s) {
        const uint32_t st = kvBase + s * KVSTG;
        #pragma unroll
        for (int i = 0; i < 4; i++) {
            const int id   = tid + 256 * i;
            const int tile = id >> 9;
            const int r    = (id >> 3) & 63;
            const int seg  = id & 7;
            const __nv_bfloat16* g = (tile ? Kl_ : Kh_)
                + base + (size_t)(kt * 64 + r) * DD + seg * 8;
            CP16(st + tile * KTILE_B + r * 144 + seg * 16, g);
        }
    };

    const int vrow = (tid & 31) * 2;
    const int dblk = tid >> 5;
    uint4 vh0, vh1, vl0, vl1;
    auto ldgV = [&](int kt) {
        const __nv_bfloat16* gh = Vh_ + base + (size_t)(kt * 64 + vrow) * DD + dblk * 8;
        const __nv_bfloat16* gl = Vl_ + base + (size_t)(kt * 64 + vrow) * DD + dblk * 8;
        vh0 = *(const uint4*)gh;  vh1 = *(const uint4*)(gh + DD);
        vl0 = *(const uint4*)gl;  vl1 = *(const uint4*)(gl + DD);
    };
    auto stsV = [&](int s) {
        const uint32_t st = kvBase + s * KVSTG;
        const uint16_t* h0p = (const uint16_t*)&vh0;
        const uint16_t* h1p = (const uint16_t*)&vh1;
        const uint16_t* l0p = (const uint16_t*)&vl0;
        const uint16_t* l1p = (const uint16_t*)&vl1;
        #pragma unroll
        for (int d = 0; d < 8; d++) {
            const uint32_t off = (uint32_t)((dblk * 8 + d) * 144 + vrow * 2);
            *(uint32_t*)(sm + (st - sb) + 2 * KTILE_B + off) =
                (uint32_t)h0p[d] | ((uint32_t)h1p[d] << 16);
            *(uint32_t*)(sm + (st - sb) + 3 * KTILE_B + off) =
                (uint32_t)l0p[d] | ((uint32_t)l1p[d] << 16);
        }
    };

    const int r0 = lane >> 2;
    unsigned char pm[2];
    pm[0] = mask[(size_t)b * SS + qt * 128 + w * 16 + r0];
    pm[1] = mask[(size_t)b * SS + qt * 128 + w * 16 + r0 + 8];

    float m_r[2] = {-1e30f, -1e30f};
    float l_r[2] = {0.f, 0.f};
    float acc_o[8][4] = {};

    const float NEGV  = -4294967295.0f;
    const float scale = 1.0f / 8.000001f;

    const int arow   = lane & 15;
    const int acb    = ((lane >> 4) * 8) * 2;
    const int qq     = lane >> 3;
    const int lr     = lane & 7;
    const int brow_q = ((qq & 2) ? 8 : 0) + lr;
    const int bcb    = ((qq & 1) * 8) * 2;

    issueK(0, 0); CP_COMMIT();
    ldgV(0);
    CP_WAIT0();
    __syncthreads();
    stsV(0);

    uint32_t qfh[4][4], qfl[4][4];
    #pragma unroll
    for (int ks = 0; ks < 4; ks++) {
        const uint32_t off = (uint32_t)((w * 16 + arow) * 144 + ks * 32 + acb);
        LDSM_X4(qfh[ks][0], qfh[ks][1], qfh[ks][2], qfh[ks][3], uQh + off);
        LDSM_X4(qfl[ks][0], qfl[ks][1], qfl[ks][2], qfl[ks][3], uQl + off);
    }
    __syncthreads();

    const int kmax = 2 * qt + 1;
    for (int kt = 0; kt <= kmax; kt++) {
        const int s = kt & 1;
        const uint32_t st = kvBase + s * KVSTG;
        const uint32_t uKh = st;
        const uint32_t uKl = st + KTILE_B;
        const uint32_t uVh = st + 2 * KTILE_B;
        const uint32_t uVl = st + 3 * KTILE_B;

        if (kt < kmax) {
            issueK(kt + 1, s ^ 1); CP_COMMIT();
            ldgV(kt + 1);
        }

        float sc[8][4] = {};
        #pragma unroll
        for (int ks = 0; ks < 4; ks++) {
            const int kb = ks * 32;
            uint32_t kh[4][4], kl[4][4];
            #pragma unroll
            for (int p = 0; p < 4; p++) {
                const uint32_t off = (uint32_t)((p * 16 + brow_q) * 144 + kb + bcb);
                LDSM_X4(kh[p][0], kh[p][1], kh[p][2], kh[p][3], uKh + off);
                LDSM_X4(kl[p][0], kl[p][1], kl[p][2], kl[p][3], uKl + off);
            }
            #pragma unroll
            for (int p = 0; p < 4; p++)
                #pragma unroll
                for (int hh = 0; hh < 2; hh++)
                    mma16816(sc[p * 2 + hh], qfh[ks], &kh[p][hh * 2]);
            #pragma unroll
            for (int p = 0; p < 4; p++)
                #pragma unroll
                for (int hh = 0; hh < 2; hh++)
                    mma16816(sc[p * 2 + hh], qfh[ks], &kl[p][hh * 2]);
            #pragma unroll
            for (int p = 0; p < 4; p++)
                #pragma unroll
                for (int hh = 0; hh < 2; hh++)
                    mma16816(sc[p * 2 + hh], qfl[ks], &kh[p][hh * 2]);
        }

        const int qg0 = qt * 128 + w * 16 + r0;
        #pragma unroll
        for (int nt = 0; nt < 8; nt++) {
            const int cg = kt * 64 + nt * 8 + (lane & 3) * 2;
            #pragma unroll
            for (int j = 0; j < 4; j++) {
                const int row_g = (j >> 1) ? qg0 + 8 : qg0;
                const int col_g = cg + (j & 1);
                sc[nt][j] *= scale;
                if (col_g > row_g || pm[j >> 1]) sc[nt][j] = NEGV;
            }
        }

        #pragma unroll
        for (int half = 0; half < 2; half++) {
            float tm = -1e30f;
            #pragma unroll
            for (int nt = 0; nt < 8; nt++)
                tm = fmaxf(tm, fmaxf(sc[nt][half * 2], sc[nt][half * 2 + 1]));
            tm = fmaxf(tm, __shfl_xor_sync(0xffffffffu, tm, 1));
            tm = fmaxf(tm, __shfl_xor_sync(0xffffffffu, tm, 2));
            const float mn = fmaxf(m_r[half], tm);
            const float f = __expf(m_r[half] - mn);
            float ps = 0.f;
            #pragma unroll
            for (int nt = 0; nt < 8; nt++) {
                const float p0 = __expf(sc[nt][half * 2]     - mn);
                const float p1 = __expf(sc[nt][half * 2 + 1] - mn);
                sc[nt][half * 2]     = p0;
                sc[nt][half * 2 + 1] = p1;
                ps += p0 + p1;
                acc_o[nt][half * 2]     *= f;
                acc_o[nt][half * 2 + 1] *= f;
            }
            ps += __shfl_xor_sync(0xffffffffu, ps, 1);
            ps += __shfl_xor_sync(0xffffffffu, ps, 2);
            l_r[half] = l_r[half] * f + ps;
            m_r[half] = mn;
        }

        if (kt < kmax) stsV(s ^ 1);

        #pragma unroll
        for (int ks = 0; ks < 4; ks++) {
            uint32_t ph[4], pl[4];
            const int t0 = 2 * ks, t1 = 2 * ks + 1;
            split2(sc[t0][0], sc[t0][1], ph[0], pl[0]);
            split2(sc[t0][2], sc[t0][3], ph[1], pl[1]);
            split2(sc[t1][0], sc[t1][1], ph[2], pl[2]);
            split2(sc[t1][2], sc[t1][3], ph[3], pl[3]);

            const int kb = ks * 32;
            uint32_t vh[4][4], vl[4][4];
            #pragma unroll
            for (int p = 0; p < 4; p++) {
                const uint32_t off = (uint32_t)((p * 16 + brow_q) * 144 + kb + bcb);
                LDSM_X4(vh[p][0], vh[p][1], vh[p][2], vh[p][3], uVh + off);
                LDSM_X4(vl[p][0], vl[p][1], vl[p][2], vl[p][3], uVl + off);
            }
            #pragma unroll
            for (int p = 0; p < 4; p++)
                #pragma unroll
                for (int hh = 0; hh < 2; hh++)
                    mma16816(acc_o[p * 2 + hh], ph, &vh[p][hh * 2]);
            #pragma unroll
            for (int p = 0; p < 4; p++)
                #pragma unroll
                for (int hh = 0; hh < 2; hh++)
                    mma16816(acc_o[p * 2 + hh], ph, &vl[p][hh * 2]);
            #pragma unroll
            for (int p = 0; p < 4; p++)
                #pragma unroll
                for (int hh = 0; hh < 2; hh++)
                    mma16816(acc_o[p * 2 + hh], pl, &vh[p][hh * 2]);
        }

        if (kt < kmax) {
            CP_WAIT0();
            __syncthreads();
        }
    }

    // normalize + write fp32 ctx
    const float inv0 = 1.0f / l_r[0];
    const float inv1 = 1.0f / l_r[1];
    const int row0 = qt * 128 + w * 16 + r0;
    #pragma unroll
    for (int nt = 0; nt < 8; nt++) {
        const int col = h * DK + nt * 8 + (lane & 3) * 2;
        float2 v0, v1;
        v0.x = acc_o[nt][0] * inv0;  v0.y = acc_o[nt][1] * inv0;
        v1.x = acc_o[nt][2] * inv1;  v1.y = acc_o[nt][3] * inv1;
        *(float2*)(ctx + ((size_t)b * SS + row0)     * DD + col) = v0;
        *(float2*)(ctx + ((size_t)b * SS + row0 + 8) * DD + col) = v1;
    }
}

// ---------------------------------------------------------------------------
// out = LayerNorm(X + R) * w + b
// ---------------------------------------------------------------------------
__global__ void __launch_bounds__(256) add_ln_kernel(
    const float* __restrict__ X, const float* __restrict__ R,
    const float* __restrict__ w, const float* __restrict__ bb,
    float* __restrict__ out)
{
    const int row = blockIdx.x;
    const int tid = threadIdx.x;
    const float4* x4 = (const float4*)(X + (size_t)row * DD);
    const float4* r4 = (const float4*)(R + (size_t)row * DD);
    float4 v = x4[tid];
    const float4 r = r4[tid];
    v.x += r.x; v.y += r.y; v.z += r.z; v.w += r.w;

    float sum = v.x + v.y + v.z + v.w;
    float sq  = v.x*v.x + v.y*v.y + v.z*v.z + v.w*v.w;
    #pragma unroll
    for (int off = 16; off; off >>= 1) {
        sum += __shfl_xor_sync(0xffffffffu, sum, off);
        sq  += __shfl_xor_sync(0xffffffffu, sq, off);
    }
    __shared__ float ssum[8], ssq[8];
    if ((tid & 31) == 0) { ssum[tid >> 5] = sum; ssq[tid >> 5] = sq; }
    __syncthreads();
    float tot = 0.f, totq = 0.f;
    #pragma unroll
    for (int i = 0; i < 8; i++) { tot += ssum[i]; totq += ssq[i]; }
    const float mu   = tot * (1.0f / DD);
    const float var  = totq * (1.0f / DD) - mu * mu;
    const float rstd = rsqrtf(var + 1e-5f);

    const float4 wv = ((const float4*)w)[tid];
    const float4 bv = ((const float4*)bb)[tid];
    float4 ov;
    ov.x = (v.x - mu) * rstd * wv.x + bv.x;
    ov.y = (v.y - mu) * rstd * wv.y + bv.y;
    ov.z = (v.z - mu) * rstd * wv.z + bv.z;
    ov.w = (v.w - mu) * rstd * wv.w + bv.w;
    ((float4*)(out + (size_t)row * DD))[tid] = ov;
}

// ---------------------------------------------------------------------------
extern "C" void kernel_launch(void* const* d_in, const int* in_sizes, int n_in,
                              void* d_out, int out_size)
{
    int mi = -1;
    for (int i = 0; i < n_in; i++)
        if (in_sizes[i] == BB * SS) { mi = i; break; }

    const float *Q, *K, *V, *Wq, *Wk, *Wv, *Wo, *l1w, *l1b, *l2w, *l2b, *lnw, *lnb;
    const unsigned char* mask;
    if (mi == 3) {
        Q   = (const float*)d_in[0];  K   = (const float*)d_in[1];
        V   = (const float*)d_in[2];  mask = (const unsigned char*)d_in[3];
        Wq  = (const float*)d_in[4];  Wk  = (const float*)d_in[5];
        Wv  = (const float*)d_in[6];  Wo  = (const float*)d_in[7];
        l1w = (const float*)d_in[8];  l1b = (const float*)d_in[9];
        l2w = (const float*)d_in[10]; l2b = (const float*)d_in[11];
        lnw = (const float*)d_in[12]; lnb = (const float*)d_in[13];
    } else {
        Q   = (const float*)d_in[0];  K   = (const float*)d_in[1];
        V   = (const float*)d_in[2];
        Wq  = (const float*)d_in[3];  Wk  = (const float*)d_in[4];
        Wv  = (const float*)d_in[5];  Wo  = (const float*)d_in[6];
        l1w = (const float*)d_in[7];  l1b = (const float*)d_in[8];
        l2w = (const float*)d_in[9];  l2b = (const float*)d_in[10];
        lnw = (const float*)d_in[11]; lnb = (const float*)d_in[12];
        mask = (const unsigned char*)d_in[13];
    }

    float *gA, *gB, *gC, *as_, *ws_;
    __nv_bfloat16* bf;
    int8_t *i8_, *w8_;
    cudaGetSymbolAddress((void**)&gA, g_A);
    cudaGetSymbolAddress((void**)&gB, g_B);
    cudaGetSymbolAddress((void**)&gC, g_C);
    cudaGetSymbolAddress((void**)&bf, g_bf);
    cudaGetSymbolAddress((void**)&i8_, g_i8);
    cudaGetSymbolAddress((void**)&as_, g_as);
    cudaGetSymbolAddress((void**)&w8_, g_w8);
    cudaGetSymbolAddress((void**)&ws_, g_ws);

    const size_t PSZ = (size_t)MTOK * DD;
    const size_t WSZ = (size_t)DD * DD;
    auto P  = [&](int i, int half) { return bf + ((size_t)(i * 2 + half)) * PSZ; };
    auto I1 = [&](int i) { return i8_ + (size_t)(i * 2 + 0) * PSZ; };
    auto I0 = [&](int i) { return i8_ + (size_t)(i * 2 + 1) * PSZ; };
    auto AS = [&](int i) { return as_ + (size_t)i * MTOK; };
    auto W1 = [&](int i) { return w8_ + (size_t)(i * 2 + 0) * WSZ; };
    auto W0 = [&](int i) { return w8_ + (size_t)(i * 2 + 1) * WSZ; };
    auto WS = [&](int i) { return ws_ + (size_t)i * DD; };

    cudaFuncSetAttribute(gemm_i8<false, false, false, true>,
                         cudaFuncAttributeMaxDynamicSharedMemorySize, I8_SMEM);
    cudaFuncSetAttribute(gemm_i8<false, false, true, false>,
                         cudaFuncAttributeMaxDynamicSharedMemorySize, I8_SMEM);
    cudaFuncSetAttribute(gemm_i8<true, true, true, false>,
                         cudaFuncAttributeMaxDynamicSharedMemorySize, I8_SMEM);
    cudaFuncSetAttribute(gemm_i8<true, false, true, false>,
                         cudaFuncAttributeMaxDynamicSharedMemorySize, I8_SMEM);
    cudaFuncSetAttribute(attn_mma_kernel,
                         cudaFuncAttributeMaxDynamicSharedMemorySize, ATT_SMEM);

    // --- weight prep: transpose (fp32, gB scratch) + quantize ---
    const dim3 wtGrid(DD / 32, DD / 32);
    const float* Wt[4] = {Wq, Wk, Wv, Wo};
    for (int i = 0; i < 4; i++) {
        transpose_w<<<wtGrid, dim3(32, 8)>>>(Wt[i], gB);
        quant_rows<<<DD, 256>>>(gB, W1(i), W0(i), WS(i));
    }
    quant_rows<<<DD, 256>>>(l1w, W1(4), W0(4), WS(4));   // already [N,K]
    quant_rows<<<DD, 256>>>(l2w, W1(5), W0(5), WS(5));

    // --- activation quant: raw Q,K,V inputs ---
    quant_rows<<<MTOK, 256>>>(Q, I1(0), I0(0), AS(0));
    quant_rows<<<MTOK, 256>>>(K, I1(1), I0(1), AS(1));
    quant_rows<<<MTOK, 256>>>(V, I1(2), I0(2), AS(2));

    const dim3 gGrid(DD / 128, MTOK / 128);   // (8, 128)

    // --- QKV projections -> split-bf16 outputs for attention ---
    gemm_i8<false, false, false, true><<<gGrid, 512, I8_SMEM>>>(
        I1(0), I0(0), AS(0), W1(0), W0(0), WS(0), nullptr, nullptr, P(0,0), P(0,1)); // Qp
    gemm_i8<false, false, false, true><<<gGrid, 512, I8_SMEM>>>(
        I1(1), I0(1), AS(1), W1(1), W0(1), WS(1), nullptr, nullptr, P(1,0), P(1,1)); // Kp
    gemm_i8<false, false, false, true><<<gGrid, 512, I8_SMEM>>>(
        I1(2), I0(2), AS(2), W1(2), W0(2), WS(2), nullptr, nullptr, P(2,0), P(2,1)); // Vp

    // --- attention -> fp32 ctx in gA ---
    attn_mma_kernel<<<dim3(SS / 128, BB * HH), 256, ATT_SMEM>>>(
        P(0,0), P(0,1), P(1,0), P(1,1), P(2,0), P(2,1), mask, gA);

    // --- output projection: quantize ctx, gemm -> gC ---
    quant_rows<<<MTOK, 256>>>(gA, I1(0), I0(0), AS(0));
    gemm_i8<false, false, true, false><<<gGrid, 512, I8_SMEM>>>(
        I1(0), I0(0), AS(0), W1(3), W0(3), WS(3), nullptr, gC, nullptr, nullptr);

    // --- X = LN(V_att + Q) -> gB ---
    add_ln_kernel<<<MTOK, 256>>>(gC, Q, lnw, lnb, gB);

    // --- FFN ---
    quant_rows<<<MTOK, 256>>>(gB, I1(1), I0(1), AS(1));
    gemm_i8<true, true, true, false><<<gGrid, 512, I8_SMEM>>>(
        I1(1), I0(1), AS(1), W1(4), W0(4), WS(4), l1b, gC, nullptr, nullptr);
    quant_rows<<<MTOK, 256>>>(gC, I1(2), I0(2), AS(2));
    gemm_i8<true, false, true, false><<<gGrid, 512, I8_SMEM>>>(
        I1(2), I0(2), AS(2), W1(5), W0(5), WS(5), l2b, gA, nullptr, nullptr);

    // --- out = LN(ffn + X) ---
    add_ln_kernel<<<MTOK, 256>>>(gA, gB, lnw, lnb, (float*)d_out);
}